// round 16
// baseline (speedup 1.0000x reference)
#include <cuda_runtime.h>

#define NB 4
#define NA 100000
#define NM 32
#define NC 80
#define TPB 256
#define NBLK_X ((NA + TPB - 1) / TPB)     // 391
#define TOTAL_BLOCKS (NBLK_X * NB)        // 1564
#define NSLOT 8                           // smem slots per thread (recycled)
#define NEG_W (-0.51986038543f)           /* -0.75 * ln(2) */
#define POS_W (-0.17328679514f)           /* -0.25 * ln(2) */
#define PMAX (1.0f - 1.0e-4f)
#define FULL 0xffffffffu

// [0]=cls_sum, [1]=reg_sum, [2]=num_pos  (zero-init; reset by finalizer block)
__device__ double g_acc[3];
__device__ unsigned int g_count;

__device__ __forceinline__ float warp_sum(float v) {
    #pragma unroll
    for (int o = 16; o > 0; o >>= 1) v += __shfl_down_sync(FULL, v, o);
    return v;
}

__device__ __forceinline__ float huber(float x) {
    float d = fabsf(x);
    return (d < (1.0f / 9.0f)) ? 4.5f * d * d : d - (0.5f / 9.0f);
}

// negative-class focal term (weight applied by caller)
__device__ __forceinline__ float nt(float p) {
    float pu = fminf(p, PMAX);
    return pu * pu * __log2f(1.0f - pu);
}

__device__ __forceinline__ float sum4(float4 v) {
    return (nt(v.x) + nt(v.y)) + (nt(v.z) + nt(v.w));
}

__global__ __launch_bounds__(TPB, 6) void fused_loss_kernel(
    const float*  __restrict__ cls_f,      // (B, A, 80)
    const float4* __restrict__ regression, // (B, A)
    const float4* __restrict__ anchors,    // (A)
    const float*  __restrict__ annotations,// (B, M, 5)
    float* __restrict__ out)
{
    __shared__ float4 sstage[NSLOT * TPB];  // 32KB recycled cp.async staging
    __shared__ float4 sb4[NM];
    __shared__ float  sarea[NM];
    __shared__ float  scls[NM];
    __shared__ float  sred[24];

    const int b    = blockIdx.y;
    const int tid  = threadIdx.x;
    const int lane = tid & 31;
    const int wrp  = tid >> 5;
    const int warp_a0 = blockIdx.x * TPB + wrp * 32;
    const int a    = warp_a0 + lane;
    const bool wactive = (warp_a0 < NA);   // tail warp-aligned (160 = 5*32)

    // cp.async helpers: slot for batch k is (k & 7); per-thread slot ownership
#define CP16(k) do { \
        unsigned sa = (unsigned)__cvta_generic_to_shared(&sstage[((k) & 7) * TPB + tid]); \
        asm volatile("cp.async.cg.shared.global [%0], [%1], 16;" \
                     :: "r"(sa), "l"(slab + 32 * (k)) : "memory"); \
    } while (0)
#define CPCOMMIT() asm volatile("cp.async.commit_group;" ::: "memory")
#define CPWAIT(n)  asm volatile("cp.async.wait_group %0;" :: "n"(n) : "memory")

    // shfl-index identity: (lane+32k)/20 == Bidx[k%5] + 8*(k/5)   (exact)
    unsigned Bidx[5];
    #pragma unroll
    for (int r = 0; r < 5; r++) Bidx[r] = ((unsigned)lane + 32u * r) / 20u;

    // ---- issue batches 0..7 immediately (in flight through annotations + IoU) ----
    const float4* slab = (const float4*)cls_f + ((size_t)b * NA + warp_a0) * 20 + lane;
    if (wactive) {
        #pragma unroll
        for (int k = 0; k < 8; k++) CP16(k);
        CPCOMMIT();                       // G0
    }

    if (tid < NM) {
        const float* ap = annotations + (b * NM + tid) * 5;
        float x1 = ap[0], y1 = ap[1], x2 = ap[2], y2 = ap[3];
        sb4[tid]   = make_float4(x1, y1, x2, y2);
        sarea[tid] = (x2 - x1) * (y2 - y1);
        scls[tid]  = ap[4];
    }
    __syncthreads();

    float cls_acc = 0.0f, reg_acc = 0.0f, pos_acc = 0.0f;

    if (wactive) {
        // ---- Phase A: per-thread IoU argmax (division-free); `an` not kept live ----
        float w;
        int best = 0;
        bool is_pos;
        {
            float4 an = anchors[a];
            float area_a = (an.z - an.x) * (an.w - an.y);
            float ib = -1.0f, ub = 1.0f;
            #pragma unroll
            for (int m = 0; m < NM; m++) {
                float4 bx = sb4[m];
                float iw = fminf(an.z, bx.z) - fmaxf(an.x, bx.x);
                float ih = fminf(an.w, bx.w) - fmaxf(an.y, bx.y);
                float inter = fmaxf(iw, 0.0f) * fmaxf(ih, 0.0f);
                float uni = area_a + sarea[m] - inter;
                if (inter * ub > ib * uni) { ib = inter; ub = uni; best = m; }
            }
            float best_iou = ib / fmaxf(ub, 1e-8f);
            bool pos = best_iou >= 0.5f;
            bool ign = (best_iou > 0.4f) && !pos;
            float cx = (an.x + an.z) * 0.5f;
            float cy = (an.y + an.w) * 0.5f;
            bool inside = (cx >= 0.0f) && (cx < 800.0f) && (cy >= 0.0f) && (cy < 800.0f);
            bool valid = inside && !ign;
            is_pos = inside && pos;
            w = valid ? NEG_W : 0.0f;
        }

        // ---- Phase B: rolling per-thread cp.async double-buffer ----
        float acc = 0.0f;

#define CONSUME(k) do { \
            float4 v = sstage[((k) & 7) * TPB + tid]; \
            float wk = __shfl_sync(FULL, w, Bidx[(k) % 5] + 8 * ((k) / 5)); \
            acc = fmaf(sum4(v), wk, acc); \
        } while (0)

        CPWAIT(0);                         // G0 (batches 0..7) landed
        #pragma unroll
        for (int k = 0; k < 4; k++) CONSUME(k);
        #pragma unroll
        for (int k = 8; k < 12; k++) CP16(k);
        CPCOMMIT();                        // G1 = batches 8..11 -> slots 0..3
        #pragma unroll
        for (int k = 4; k < 8; k++) CONSUME(k);
        #pragma unroll
        for (int k = 12; k < 16; k++) CP16(k);
        CPCOMMIT();                        // G2 = batches 12..15 -> slots 4..7
        CPWAIT(1);                         // G1 landed
        #pragma unroll
        for (int k = 8; k < 12; k++) CONSUME(k);
        #pragma unroll
        for (int k = 16; k < 20; k++) CP16(k);
        CPCOMMIT();                        // G3 = batches 16..19 -> slots 0..3
        CPWAIT(1);                         // G2 landed
        #pragma unroll
        for (int k = 12; k < 16; k++) CONSUME(k);
        CPWAIT(0);                         // G3 landed
        #pragma unroll
        for (int k = 16; k < 20; k++) CONSUME(k);

        cls_acc = acc;

        // ---- positive-anchor extras (rare path; reloads anchor) ----
        if (is_pos) {
            pos_acc = 1.0f;
            float4 an = anchors[a];
            float4 bx = sb4[best];
            float aw = an.z - an.x, ah = an.w - an.y;
            float t0 = ((bx.x - an.x) / aw) * 5.0f;
            float t1 = ((bx.y - an.y) / ah) * 5.0f;
            float t2 = ((bx.z - an.z) / aw) * 5.0f;
            float t3 = ((bx.w - an.w) / ah) * 5.0f;
            float4 r = regression[(size_t)b * NA + a];
            reg_acc = huber(r.x - t0) + huber(r.y - t1) + huber(r.z - t2) + huber(r.w - t3);

            // correction: + true positive-label term, − the negative term added above
            int lc = (int)scls[best];
            float p = cls_f[((size_t)b * NA + a) * NC + lc];
            float pc = fminf(fmaxf(p, 1.0e-4f), PMAX);
            float q = 1.0f - pc;
            cls_acc += POS_W * q * q * __log2f(pc) - NEG_W * nt(p);
        }
    }

    // ---- Phase C: block reduce (8 warps), 3 double atomics, last-block finalize ----
    float wc = warp_sum(cls_acc);
    float wr = warp_sum(reg_acc);
    float wp = warp_sum(pos_acc);
    if (lane == 0) { sred[wrp] = wc; sred[8 + wrp] = wr; sred[16 + wrp] = wp; }
    __syncthreads();
    if (wrp == 0) {
        float vc = (lane < 8) ? sred[lane] : 0.0f;
        float vr = (lane < 8) ? sred[8 + lane] : 0.0f;
        float vp = (lane < 8) ? sred[16 + lane] : 0.0f;
        vc = warp_sum(vc); vr = warp_sum(vr); vp = warp_sum(vp);
        if (lane == 0) {
            atomicAdd(&g_acc[0], (double)vc);
            if (vr != 0.0f) atomicAdd(&g_acc[1], (double)vr);
            if (vp != 0.0f) atomicAdd(&g_acc[2], (double)vp);
            __threadfence();
            unsigned int done = atomicAdd(&g_count, 1u);
            if (done == TOTAL_BLOCKS - 1) {
                double np = g_acc[2];
                if (np < 1.0) np = 1.0;
                out[0] = (float)((g_acc[0] + g_acc[1]) / np);
                g_acc[0] = 0.0; g_acc[1] = 0.0; g_acc[2] = 0.0;
                __threadfence();
                g_count = 0u;
            }
        }
    }
}

extern "C" void kernel_launch(void* const* d_in, const int* in_sizes, int n_in,
                              void* d_out, int out_size) {
    const float* cls = (const float*)d_in[0];  // (B, A, 80)
    const float* reg = (const float*)d_in[1];  // (B, A, 4)
    const float* anc = (const float*)d_in[2];  // (A, 4)
    const float* ann = (const float*)d_in[3];  // (B, M, 5)

    dim3 grid(NBLK_X, NB);
    fused_loss_kernel<<<grid, TPB>>>(
        cls, (const float4*)reg, (const float4*)anc, ann, (float*)d_out);
}